// round 2
// baseline (speedup 1.0000x reference)
#include <cuda_runtime.h>
#include <math.h>

#define IMG 120
#define GT 1024
#define PP 1024
#define NB 8

// ---------------- scratch (device globals; no allocations allowed) ----------
__device__ __align__(16) float g_h1[NB * 8 * 57 * 57];   // conv1 pooled output
__device__ __align__(16) float g_h2[NB * 10 * 26 * 26];  // conv2 pooled (== flatten)
__device__ __align__(16) float g_fc1[NB * 32];           // relu(fc1)
__device__ __align__(16) float g_T[NB * 12];             // T_theta
__device__ __align__(16) float g_vals[NB * PP * 3];      // sampled values
__device__ int   g_idx[PP];                              // px*GT + py per point
__device__ float g_const[NB * 3];                        // center bilinear const

// ---------------- conv1 + maxpool2 + relu -----------------------------------
// x: (8,3,120,120), w: (8,3,7,7). conv VALID -> (114,114), pool2 -> (57,57).
// One thread per (n, oy, ox) pooled pixel; all 8 oc + 4 pool quadrants in regs.
__global__ void conv1_kernel(const float* __restrict__ x,
                             const float* __restrict__ w,
                             const float* __restrict__ b) {
    __shared__ float sw[8 * 3 * 49];
    __shared__ float sb[8];
    for (int i = threadIdx.x; i < 8 * 3 * 49; i += blockDim.x) sw[i] = w[i];
    if (threadIdx.x < 8) sb[threadIdx.x] = b[threadIdx.x];
    __syncthreads();

    int tid = blockIdx.x * blockDim.x + threadIdx.x;
    if (tid >= NB * 57 * 57) return;
    int n = tid / (57 * 57);
    int r = tid % (57 * 57);
    int oy = r / 57, ox = r % 57;

    float acc[8][4];
#pragma unroll
    for (int oc = 0; oc < 8; oc++)
#pragma unroll
        for (int q = 0; q < 4; q++) acc[oc][q] = 0.f;

    const float* xb = x + (size_t)n * 3 * IMG * IMG + (2 * oy) * IMG + 2 * ox;
    for (int kc = 0; kc < 3; kc++) {
        const float* xc = xb + kc * IMG * IMG;
        for (int ky = 0; ky < 7; ky++) {
            const float* xr = xc + ky * IMG;
#pragma unroll
            for (int kx = 0; kx < 7; kx++) {
                float x00 = xr[kx];
                float x01 = xr[kx + 1];
                float x10 = xr[kx + IMG];
                float x11 = xr[kx + IMG + 1];
#pragma unroll
                for (int oc = 0; oc < 8; oc++) {
                    float wv = sw[(oc * 3 + kc) * 49 + ky * 7 + kx];
                    acc[oc][0] = fmaf(wv, x00, acc[oc][0]);
                    acc[oc][1] = fmaf(wv, x01, acc[oc][1]);
                    acc[oc][2] = fmaf(wv, x10, acc[oc][2]);
                    acc[oc][3] = fmaf(wv, x11, acc[oc][3]);
                }
            }
        }
    }
#pragma unroll
    for (int oc = 0; oc < 8; oc++) {
        float v = fmaxf(fmaxf(acc[oc][0], acc[oc][1]),
                        fmaxf(acc[oc][2], acc[oc][3])) + sb[oc];
        g_h1[((n * 8 + oc) * 57 + oy) * 57 + ox] = fmaxf(v, 0.f);
    }
}

// ---------------- conv2 + maxpool2 + relu (4-way kc-split) -------------------
// in: (8,8,57,57), w: (10,8,5,5). conv VALID -> (53,53), pool2 -> (26,26).
// 4 consecutive lanes cooperate on one pooled pixel: lane&3 picks 2 of 8 input
// channels; partial acc[10][4] combined via shfl_xor, lane&3==0 writes.
// Grid: NB*676*4 = 21632 threads = 169 blocks of 128 (exact, no stragglers).
__global__ void conv2_kernel(const float* __restrict__ w,
                             const float* __restrict__ b) {
    __shared__ float sw[10 * 8 * 25];
    __shared__ float sb[10];
    for (int i = threadIdx.x; i < 10 * 8 * 25; i += blockDim.x) sw[i] = w[i];
    if (threadIdx.x < 10) sb[threadIdx.x] = b[threadIdx.x];
    __syncthreads();

    int t = blockIdx.x * blockDim.x + threadIdx.x;   // 0 .. 21631
    int split = t & 3;                                // 2 kc per split
    int pix = t >> 2;                                 // 0 .. 5407
    int n = pix / 676;
    int r = pix % 676;
    int oy = r / 26, ox = r % 26;

    float acc[10][4];
#pragma unroll
    for (int oc = 0; oc < 10; oc++)
#pragma unroll
        for (int q = 0; q < 4; q++) acc[oc][q] = 0.f;

    const float* xb = g_h1 + (size_t)n * 8 * 57 * 57 + (2 * oy) * 57 + 2 * ox;
#pragma unroll
    for (int kk = 0; kk < 2; kk++) {
        int kc = split * 2 + kk;
        const float* xc = xb + kc * 57 * 57;
#pragma unroll
        for (int ky = 0; ky < 5; ky++) {
            const float* xr = xc + ky * 57;
#pragma unroll
            for (int kx = 0; kx < 5; kx++) {
                float x00 = xr[kx];
                float x01 = xr[kx + 1];
                float x10 = xr[kx + 57];
                float x11 = xr[kx + 58];
#pragma unroll
                for (int oc = 0; oc < 10; oc++) {
                    float wv = sw[(oc * 8 + kc) * 25 + ky * 5 + kx];
                    acc[oc][0] = fmaf(wv, x00, acc[oc][0]);
                    acc[oc][1] = fmaf(wv, x01, acc[oc][1]);
                    acc[oc][2] = fmaf(wv, x10, acc[oc][2]);
                    acc[oc][3] = fmaf(wv, x11, acc[oc][3]);
                }
            }
        }
    }

    // combine the 4 kc-splits (lanes p*4..p*4+3) via butterfly shuffles
#pragma unroll
    for (int oc = 0; oc < 10; oc++)
#pragma unroll
        for (int q = 0; q < 4; q++) {
            float v = acc[oc][q];
            v += __shfl_xor_sync(0xffffffffu, v, 1);
            v += __shfl_xor_sync(0xffffffffu, v, 2);
            acc[oc][q] = v;
        }

    if (split == 0) {
#pragma unroll
        for (int oc = 0; oc < 10; oc++) {
            float v = fmaxf(fmaxf(acc[oc][0], acc[oc][1]),
                            fmaxf(acc[oc][2], acc[oc][3])) + sb[oc];
            // layout: n*6760 + oc*676 + oy*26 + ox (matches jnp reshape)
            g_h2[((n * 10 + oc) * 26 + oy) * 26 + ox] = fmaxf(v, 0.f);
        }
    }
}

// ---------------- FC1: (8,6760) @ (6760,32)^T + relu ------------------------
// one block per (n, j) output; float4 strided dot + warp/smem reduction.
__global__ void fc1_kernel(const float* __restrict__ w,
                           const float* __restrict__ b) {
    int blk = blockIdx.x;
    int n = blk >> 5;
    int j = blk & 31;
    const float4* wr = reinterpret_cast<const float4*>(w + (size_t)j * 6760);
    const float4* hr = reinterpret_cast<const float4*>(g_h2 + (size_t)n * 6760);
    float s = 0.f;
    for (int i = threadIdx.x; i < 1690; i += 128) {   // 6760/4
        float4 a = wr[i], c = hr[i];
        s = fmaf(a.x, c.x, s);
        s = fmaf(a.y, c.y, s);
        s = fmaf(a.z, c.z, s);
        s = fmaf(a.w, c.w, s);
    }
#pragma unroll
    for (int off = 16; off > 0; off >>= 1)
        s += __shfl_xor_sync(0xffffffffu, s, off);
    __shared__ float red[4];
    if ((threadIdx.x & 31) == 0) red[threadIdx.x >> 5] = s;
    __syncthreads();
    if (threadIdx.x == 0)
        g_fc1[n * 32 + j] =
            fmaxf(red[0] + red[1] + red[2] + red[3] + b[j], 0.f);
}

// ---------------- FC2 + Rodrigues + T_theta + center constants --------------
__global__ void head2_kernel(const float* __restrict__ w2,
                             const float* __restrict__ b2,
                             const float* __restrict__ x,
                             float* __restrict__ out) {
    __shared__ float sth[56];
    int t = threadIdx.x;
    if (t < 56) {
        int n = t / 7, i = t % 7;
        float s = b2[i];
        for (int j = 0; j < 32; j++)
            s = fmaf(g_fc1[n * 32 + j], w2[i * 32 + j], s);
        sth[t] = s;
    }
    __syncthreads();
    if (t < 8) {
        const float* th = &sth[t * 7];
        float sc = fabsf(th[0]);
        float vx = th[1], vy = th[2], vz = th[3];
        float ang = sqrtf(vx * vx + vy * vy + vz * vz + 1e-8f);
        float kx = vx / ang, ky = vy / ang, kz = vz / ang;
        float sn = sinf(ang);
        float cc = 1.f - cosf(ang);
        float R[3][3];
        R[0][0] = 1.f - cc * (ky * ky + kz * kz);
        R[0][1] = sn * (-kz) + cc * (kx * ky);
        R[0][2] = sn * (ky) + cc * (kx * kz);
        R[1][0] = sn * (kz) + cc * (kx * ky);
        R[1][1] = 1.f - cc * (kx * kx + kz * kz);
        R[1][2] = sn * (-kx) + cc * (ky * kz);
        R[2][0] = sn * (-ky) + cc * (kx * kz);
        R[2][1] = sn * (kx) + cc * (ky * kz);
        R[2][2] = 1.f - cc * (kx * kx + ky * ky);
#pragma unroll
        for (int i = 0; i < 3; i++) {
#pragma unroll
            for (int j = 0; j < 3; j++) {
                float v = R[i][j] * sc;
                g_T[t * 12 + i * 4 + j] = v;
                out[t * 12 + i * 4 + j] = v;
            }
            float v3 = th[4 + i];
            g_T[t * 12 + i * 4 + 3] = v3;
            out[t * 12 + i * 4 + 3] = v3;
        }
    }
    if (t < 24) {
        // grid == 0 samples image center: ix=iy=59.5 -> mean of 4 center px
        int n = t / 3, c = t % 3;
        const float* xp = x + (((size_t)n * 3 + c) * IMG + 59) * IMG + 59;
        g_const[t] = 0.25f * (xp[0] + xp[1] + xp[IMG] + xp[IMG + 1]);
    }
}

// ---------------- projection + bilinear sample of scattered points ----------
__global__ void proj_kernel(const float* __restrict__ x,
                            const float* __restrict__ uv,
                            const float* __restrict__ xyz) {
    int t = blockIdx.x * blockDim.x + threadIdx.x;
    if (t >= NB * PP) return;
    int n = t >> 10, p = t & 1023;
    const float* T = g_T + n * 12;
    float X = xyz[p * 3], Y = xyz[p * 3 + 1], Z = xyz[p * 3 + 2];
    float p0 = T[0] * X + T[1] * Y + T[2] * Z + T[3];
    float p1 = T[4] * X + T[5] * Y + T[6] * Z + T[7];
    float xs = p0 / (float)IMG * 2.0f - 1.0f;
    float ys = -(p1 / (float)IMG * 2.0f - 1.0f);
    float ix = ((xs + 1.0f) * (float)IMG - 1.0f) * 0.5f;
    float iy = ((ys + 1.0f) * (float)IMG - 1.0f) * 0.5f;
    float ix0 = floorf(ix), iy0 = floorf(iy);
    float fx = ix - ix0, fy = iy - iy0;
    float v0 = 0.f, v1 = 0.f, v2 = 0.f;
    const float* xb = x + (size_t)n * 3 * IMG * IMG;

#define CORNER(IYF, IXF, WT)                                              \
    {                                                                     \
        float wv = (WT);                                                  \
        float iyf = (IYF), ixf = (IXF);                                   \
        if (ixf >= 0.f && ixf < (float)IMG && iyf >= 0.f &&               \
            iyf < (float)IMG) {                                           \
            int ii = (int)ixf, jj = (int)iyf;                             \
            const float* pc = xb + jj * IMG + ii;                         \
            v0 = fmaf(pc[0], wv, v0);                                     \
            v1 = fmaf(pc[IMG * IMG], wv, v1);                             \
            v2 = fmaf(pc[2 * IMG * IMG], wv, v2);                         \
        }                                                                 \
    }
    CORNER(iy0,       ix0,       (1.f - fy) * (1.f - fx));
    CORNER(iy0,       ix0 + 1.f, (1.f - fy) * fx);
    CORNER(iy0 + 1.f, ix0,       fy * (1.f - fx));
    CORNER(iy0 + 1.f, ix0 + 1.f, fy * fx);
#undef CORNER

    g_vals[t * 3 + 0] = v0;
    g_vals[t * 3 + 1] = v1;
    g_vals[t * 3 + 2] = v2;
    if (n == 0) {
        int px = (int)floorf(uv[p * 2] * (float)GT);
        int py = (int)floorf(uv[p * 2 + 1] * (float)GT);
        g_idx[p] = px * GT + py;
    }
}

// ---------------- constant fill of aligned_x (the HBM-bound part) -----------
// 6,291,456 float4; each thread writes 4 consecutive float4 (64 B).
__global__ void fill_kernel(float* __restrict__ out) {
    int gid = blockIdx.x * blockDim.x + threadIdx.x;
    long base = (long)gid * 4;                 // float4 index
    int plane = (int)(base >> 18);             // 262144 float4 per (n,c) plane
    float v = g_const[plane];
    float4 vv = make_float4(v, v, v, v);
    float4* o = reinterpret_cast<float4*>(out) + base;
    o[0] = vv; o[1] = vv; o[2] = vv; o[3] = vv;
}

// ---------------- scatter of sampled values ---------------------------------
__global__ void scatter_kernel(float* __restrict__ out) {
    int t = blockIdx.x * blockDim.x + threadIdx.x;
    if (t >= NB * PP * 3) return;
    int c = t % 3;
    int p = (t / 3) % PP;
    int n = t / (3 * PP);
    out[(long)(n * 3 + c) * (GT * GT) + g_idx[p]] =
        g_vals[(n * PP + p) * 3 + c];
}

// ---------------- launch -----------------------------------------------------
extern "C" void kernel_launch(void* const* d_in, const int* in_sizes, int n_in,
                              void* d_out, int out_size) {
    const float* x   = (const float*)d_in[0];
    const float* uv  = (const float*)d_in[1];
    const float* xyz = (const float*)d_in[2];
    const float* w1  = (const float*)d_in[3];
    const float* b1  = (const float*)d_in[4];
    const float* w2  = (const float*)d_in[5];
    const float* b2  = (const float*)d_in[6];
    const float* wf1 = (const float*)d_in[7];
    const float* bf1 = (const float*)d_in[8];
    const float* wf2 = (const float*)d_in[9];
    const float* bf2 = (const float*)d_in[10];
    float* out = (float*)d_out;

    conv1_kernel<<<(NB * 57 * 57 + 127) / 128, 128>>>(x, w1, b1);
    conv2_kernel<<<NB * 676 * 4 / 128, 128>>>(w2, b2);   // 169 blocks exact
    fc1_kernel<<<256, 128>>>(wf1, bf1);
    head2_kernel<<<1, 64>>>(wf2, bf2, x, out);
    proj_kernel<<<(NB * PP + 255) / 256, 256>>>(x, uv, xyz);
    // aligned_x region starts right after the 96 T_theta floats (16B aligned)
    fill_kernel<<<6144, 256>>>(out + 96);
    scatter_kernel<<<(NB * PP * 3 + 255) / 256, 256>>>(out + 96);
}